// round 11
// baseline (speedup 1.0000x reference)
#include <cuda_runtime.h>

#define B_SZ   4
#define S_LEN  4096
#define D_DIM  512
#define H_DIM  64
#define NT     (B_SZ * S_LEN)   // 16384 total tokens

// Scratch (device globals — no allocations allowed in kernel_launch)
__device__ float g_Q [B_SZ * S_LEN * H_DIM];   // [b][s][h]
__device__ float g_Kt[B_SZ * H_DIM * S_LEN];   // [b][h][s]  (pre-transposed K)
__device__ float g_V [B_SZ * S_LEN * H_DIM];   // [b][s][h]
__device__ float g_O [B_SZ * S_LEN * H_DIM];   // [b][s][h]

// ---------------------------------------------------------------------------
// C[M,N] = A[M,K] @ W[K,N] + bias
// out_mode 0: C[m*N + n]
// out_mode 1: scatter to [b][n][s] with b = m / S_LEN, s = m % S_LEN  (K transpose)
// Requires M%64==0, N%64==0, K%64==0. Block = 256 threads, 64x64 tile, 4x4/thread.
// ---------------------------------------------------------------------------
__global__ __launch_bounds__(256) void gemm_bias_kernel(
    const float* __restrict__ A,
    const float* __restrict__ W,
    const float* __restrict__ bias,
    float* __restrict__ C,
    int M, int N, int K, int out_mode)
{
    __shared__ float As[64][64];
    __shared__ float Ws[64][64];
    const int tid = threadIdx.x;
    const int tx = tid & 15, ty = tid >> 4;
    const int m0 = blockIdx.y * 64;
    const int n0 = blockIdx.x * 64;

    float acc[4][4] = {};

    for (int k0 = 0; k0 < K; k0 += 64) {
        #pragma unroll
        for (int u = 0; u < 4; u++) {
            int t = tid + u * 256;
            int r = t >> 4, c = (t & 15) << 2;
            *(float4*)&As[r][c] = *(const float4*)&A[(size_t)(m0 + r) * K + k0 + c];
            *(float4*)&Ws[r][c] = *(const float4*)&W[(size_t)(k0 + r) * N + n0 + c];
        }
        __syncthreads();

        #pragma unroll 8
        for (int kk = 0; kk < 64; kk++) {
            float4 wv = *(float4*)&Ws[kk][tx << 2];
            float a0 = As[(ty << 2) + 0][kk];
            float a1 = As[(ty << 2) + 1][kk];
            float a2 = As[(ty << 2) + 2][kk];
            float a3 = As[(ty << 2) + 3][kk];
            acc[0][0] += a0 * wv.x; acc[0][1] += a0 * wv.y; acc[0][2] += a0 * wv.z; acc[0][3] += a0 * wv.w;
            acc[1][0] += a1 * wv.x; acc[1][1] += a1 * wv.y; acc[1][2] += a1 * wv.z; acc[1][3] += a1 * wv.w;
            acc[2][0] += a2 * wv.x; acc[2][1] += a2 * wv.y; acc[2][2] += a2 * wv.z; acc[2][3] += a2 * wv.w;
            acc[3][0] += a3 * wv.x; acc[3][1] += a3 * wv.y; acc[3][2] += a3 * wv.z; acc[3][3] += a3 * wv.w;
        }
        __syncthreads();
    }

    #pragma unroll
    for (int ii = 0; ii < 4; ii++) {
        int m = m0 + (ty << 2) + ii;
        #pragma unroll
        for (int jj = 0; jj < 4; jj++) {
            int n = n0 + (tx << 2) + jj;
            float v = acc[ii][jj] + bias[n];
            if (out_mode == 0) {
                C[(size_t)m * N + n] = v;
            } else {
                int b = m >> 12;            // S_LEN = 4096 = 2^12
                int s = m & 4095;
                C[(((size_t)(b * H_DIM + n)) << 12) + s] = v;
            }
        }
    }
}

// ---------------------------------------------------------------------------
// Fused causal flash attention over g_Q / g_Kt / g_V -> g_O.
// Br = Bc = 64, 256 threads (tx=k/h dim, ty=q dim), 4x4 per thread.
// Scores pre-scaled by 1/64 (reference divides by sqrt(S) = 64).
// Dynamic smem: Qs | Kst | Vs | Ps, 4 * 64*64 floats = 64 KB.
// ---------------------------------------------------------------------------
__global__ __launch_bounds__(256, 3) void attn_kernel()
{
    extern __shared__ float sm[];
    float (*Qs)[64]  = (float(*)[64])(sm);
    float (*Kst)[64] = (float(*)[64])(sm + 4096);   // [h][k]
    float (*Vs)[64]  = (float(*)[64])(sm + 8192);   // [k][h]
    float (*Ps)[64]  = (float(*)[64])(sm + 12288);  // [q][k]

    const int b   = blockIdx.y;
    const int qi  = (gridDim.x - 1) - blockIdx.x;   // longest blocks launch first
    const int tid = threadIdx.x;
    const int tx  = tid & 15, ty = tid >> 4;

    // Load Q tile, pre-scaled by 1/64
    const float* Qp = g_Q + ((size_t)(b * S_LEN + qi * 64)) * H_DIM;
    #pragma unroll
    for (int u = 0; u < 4; u++) {
        int t = tid + u * 256;
        int r = t >> 4, c = (t & 15) << 2;
        float4 q = *(const float4*)&Qp[r * H_DIM + c];
        q.x *= 0.015625f; q.y *= 0.015625f; q.z *= 0.015625f; q.w *= 0.015625f;
        *(float4*)&Qs[r][c] = q;
    }

    float m_i[4] = {-1e30f, -1e30f, -1e30f, -1e30f};
    float l_i[4] = {0.f, 0.f, 0.f, 0.f};
    float o[4][4] = {};

    const float* Ktb = g_Kt + (size_t)b * H_DIM * S_LEN;
    const float* Vb  = g_V  + (size_t)b * S_LEN * H_DIM;

    for (int j = 0; j <= qi; j++) {
        __syncthreads();   // previous PV done reading Vs/Ps; Q load done (iter 0)
        #pragma unroll
        for (int u = 0; u < 4; u++) {
            int t = tid + u * 256;
            int r = t >> 4, c = (t & 15) << 2;
            *(float4*)&Kst[r][c] = *(const float4*)&Ktb[(size_t)r * S_LEN + j * 64 + c];
            *(float4*)&Vs[r][c]  = *(const float4*)&Vb[(size_t)(j * 64 + r) * H_DIM + c];
        }
        __syncthreads();

        // S = Q @ K^T (pre-scaled)
        float s[4][4] = {};
        #pragma unroll 8
        for (int kk = 0; kk < 64; kk++) {
            float4 kv = *(float4*)&Kst[kk][tx << 2];
            #pragma unroll
            for (int ii = 0; ii < 4; ii++) {
                float q = Qs[(ty << 2) + ii][kk];
                s[ii][0] += q * kv.x; s[ii][1] += q * kv.y;
                s[ii][2] += q * kv.z; s[ii][3] += q * kv.w;
            }
        }

        // Causal mask on the diagonal tile
        if (j == qi) {
            #pragma unroll
            for (int ii = 0; ii < 4; ii++)
                #pragma unroll
                for (int jj = 0; jj < 4; jj++)
                    if (((tx << 2) + jj) > ((ty << 2) + ii)) s[ii][jj] = -1e30f;
        }

        // Online softmax (row reduction across the 16 tx lanes; xor<16 stays in-warp)
        #pragma unroll
        for (int ii = 0; ii < 4; ii++) {
            float mx = fmaxf(fmaxf(s[ii][0], s[ii][1]), fmaxf(s[ii][2], s[ii][3]));
            #pragma unroll
            for (int off = 1; off < 16; off <<= 1)
                mx = fmaxf(mx, __shfl_xor_sync(0xffffffffu, mx, off));
            float m_new = fmaxf(m_i[ii], mx);
            float corr  = __expf(m_i[ii] - m_new);
            float rs = 0.f;
            #pragma unroll
            for (int jj = 0; jj < 4; jj++) {
                float p = __expf(s[ii][jj] - m_new);
                rs += p;
                Ps[(ty << 2) + ii][(tx << 2) + jj] = p;
            }
            #pragma unroll
            for (int off = 1; off < 16; off <<= 1)
                rs += __shfl_xor_sync(0xffffffffu, rs, off);
            l_i[ii] = l_i[ii] * corr + rs;
            m_i[ii] = m_new;
            o[ii][0] *= corr; o[ii][1] *= corr; o[ii][2] *= corr; o[ii][3] *= corr;
        }
        __syncthreads();

        // O += P @ V
        #pragma unroll 8
        for (int kk = 0; kk < 64; kk++) {
            float4 vv = *(float4*)&Vs[kk][tx << 2];
            #pragma unroll
            for (int ii = 0; ii < 4; ii++) {
                float p = Ps[(ty << 2) + ii][kk];
                o[ii][0] += p * vv.x; o[ii][1] += p * vv.y;
                o[ii][2] += p * vv.z; o[ii][3] += p * vv.w;
            }
        }
    }

    // Normalize and store
    float* Op = g_O + ((size_t)(b * S_LEN + qi * 64)) * H_DIM;
    #pragma unroll
    for (int ii = 0; ii < 4; ii++) {
        float inv = 1.0f / l_i[ii];
        float4 ov = make_float4(o[ii][0] * inv, o[ii][1] * inv,
                                o[ii][2] * inv, o[ii][3] * inv);
        *(float4*)&Op[((ty << 2) + ii) * H_DIM + (tx << 2)] = ov;
    }
}

// ---------------------------------------------------------------------------
extern "C" void kernel_launch(void* const* d_in, const int* in_sizes, int n_in,
                              void* d_out, int out_size)
{
    const float* x  = (const float*)d_in[0];
    const float* Wq = (const float*)d_in[1];
    const float* bq = (const float*)d_in[2];
    const float* Wk = (const float*)d_in[3];
    const float* bk = (const float*)d_in[4];
    const float* Wv = (const float*)d_in[5];
    const float* bv = (const float*)d_in[6];
    const float* Wo = (const float*)d_in[7];
    const float* bo = (const float*)d_in[8];
    float* out = (float*)d_out;

    float *pQ, *pKt, *pV, *pO;
    cudaGetSymbolAddress((void**)&pQ,  g_Q);
    cudaGetSymbolAddress((void**)&pKt, g_Kt);
    cudaGetSymbolAddress((void**)&pV,  g_V);
    cudaGetSymbolAddress((void**)&pO,  g_O);

    dim3 blk(256);

    // Q/K/V projections: M=16384, K=512, N=64 (K projection scatters transposed)
    gemm_bias_kernel<<<dim3(1, NT / 64), blk>>>(x, Wq, bq, pQ,  NT, H_DIM, D_DIM, 0);
    gemm_bias_kernel<<<dim3(1, NT / 64), blk>>>(x, Wk, bk, pKt, NT, H_DIM, D_DIM, 1);
    gemm_bias_kernel<<<dim3(1, NT / 64), blk>>>(x, Wv, bv, pV,  NT, H_DIM, D_DIM, 0);

    // Fused causal attention
    cudaFuncSetAttribute(attn_kernel, cudaFuncAttributeMaxDynamicSharedMemorySize, 65536);
    attn_kernel<<<dim3(S_LEN / 64, B_SZ), blk, 65536>>>();

    // Output projection: M=16384, K=64, N=512
    gemm_bias_kernel<<<dim3(D_DIM / 64, NT / 64), blk>>>(pO, Wo, bo, out, NT, D_DIM, H_DIM, 0);
}

// round 12
// speedup vs baseline: 1.0005x; 1.0005x over previous
#include <cuda_runtime.h>

#define B_SZ   4
#define S_LEN  4096
#define D_DIM  512
#define H_DIM  64
#define NT     (B_SZ * S_LEN)   // 16384 total tokens

// Scratch (device globals — no allocations allowed in kernel_launch)
__device__ float g_Q [B_SZ * S_LEN * H_DIM];   // [b][s][h]
__device__ float g_Kt[B_SZ * H_DIM * S_LEN];   // [b][h][s]  (pre-transposed K)
__device__ float g_V [B_SZ * S_LEN * H_DIM];   // [b][s][h]
__device__ float g_O [B_SZ * S_LEN * H_DIM];   // [b][s][h]

// ---------------------------------------------------------------------------
// C[M,N] = A[M,K] @ W[K,N] + bias
// out_mode 0: C[m*N + n]
// out_mode 1: scatter to [b][n][s] with b = m / S_LEN, s = m % S_LEN  (K transpose)
// Requires M%64==0, N%64==0, K%64==0. Block = 256 threads, 64x64 tile, 4x4/thread.
// ---------------------------------------------------------------------------
__global__ __launch_bounds__(256) void gemm_bias_kernel(
    const float* __restrict__ A,
    const float* __restrict__ W,
    const float* __restrict__ bias,
    float* __restrict__ C,
    int M, int N, int K, int out_mode)
{
    __shared__ float As[64][64];
    __shared__ float Ws[64][64];
    const int tid = threadIdx.x;
    const int tx = tid & 15, ty = tid >> 4;
    const int m0 = blockIdx.y * 64;
    const int n0 = blockIdx.x * 64;

    float acc[4][4] = {};

    for (int k0 = 0; k0 < K; k0 += 64) {
        #pragma unroll
        for (int u = 0; u < 4; u++) {
            int t = tid + u * 256;
            int r = t >> 4, c = (t & 15) << 2;
            *(float4*)&As[r][c] = *(const float4*)&A[(size_t)(m0 + r) * K + k0 + c];
            *(float4*)&Ws[r][c] = *(const float4*)&W[(size_t)(k0 + r) * N + n0 + c];
        }
        __syncthreads();

        #pragma unroll 8
        for (int kk = 0; kk < 64; kk++) {
            float4 wv = *(float4*)&Ws[kk][tx << 2];
            float a0 = As[(ty << 2) + 0][kk];
            float a1 = As[(ty << 2) + 1][kk];
            float a2 = As[(ty << 2) + 2][kk];
            float a3 = As[(ty << 2) + 3][kk];
            acc[0][0] += a0 * wv.x; acc[0][1] += a0 * wv.y; acc[0][2] += a0 * wv.z; acc[0][3] += a0 * wv.w;
            acc[1][0] += a1 * wv.x; acc[1][1] += a1 * wv.y; acc[1][2] += a1 * wv.z; acc[1][3] += a1 * wv.w;
            acc[2][0] += a2 * wv.x; acc[2][1] += a2 * wv.y; acc[2][2] += a2 * wv.z; acc[2][3] += a2 * wv.w;
            acc[3][0] += a3 * wv.x; acc[3][1] += a3 * wv.y; acc[3][2] += a3 * wv.z; acc[3][3] += a3 * wv.w;
        }
        __syncthreads();
    }

    #pragma unroll
    for (int ii = 0; ii < 4; ii++) {
        int m = m0 + (ty << 2) + ii;
        #pragma unroll
        for (int jj = 0; jj < 4; jj++) {
            int n = n0 + (tx << 2) + jj;
            float v = acc[ii][jj] + bias[n];
            if (out_mode == 0) {
                C[(size_t)m * N + n] = v;
            } else {
                int b = m >> 12;            // S_LEN = 4096 = 2^12
                int s = m & 4095;
                C[(((size_t)(b * H_DIM + n)) << 12) + s] = v;
            }
        }
    }
}

// ---------------------------------------------------------------------------
// Fused causal flash attention over g_Q / g_Kt / g_V -> g_O.
// Br = Bc = 64, 256 threads (tx=k/h dim, ty=q dim), 4x4 per thread.
// Scores pre-scaled by 1/64 (reference divides by sqrt(S) = 64).
// Dynamic smem: Qs | Kst | Vs | Ps, 4 * 64*64 floats = 64 KB.
// ---------------------------------------------------------------------------
__global__ __launch_bounds__(256, 3) void attn_kernel()
{
    extern __shared__ float sm[];
    float (*Qs)[64]  = (float(*)[64])(sm);
    float (*Kst)[64] = (float(*)[64])(sm + 4096);   // [h][k]
    float (*Vs)[64]  = (float(*)[64])(sm + 8192);   // [k][h]
    float (*Ps)[64]  = (float(*)[64])(sm + 12288);  // [q][k]

    const int b   = blockIdx.y;
    const int qi  = (gridDim.x - 1) - blockIdx.x;   // longest blocks launch first
    const int tid = threadIdx.x;
    const int tx  = tid & 15, ty = tid >> 4;

    // Load Q tile, pre-scaled by 1/64
    const float* Qp = g_Q + ((size_t)(b * S_LEN + qi * 64)) * H_DIM;
    #pragma unroll
    for (int u = 0; u < 4; u++) {
        int t = tid + u * 256;
        int r = t >> 4, c = (t & 15) << 2;
        float4 q = *(const float4*)&Qp[r * H_DIM + c];
        q.x *= 0.015625f; q.y *= 0.015625f; q.z *= 0.015625f; q.w *= 0.015625f;
        *(float4*)&Qs[r][c] = q;
    }

    float m_i[4] = {-1e30f, -1e30f, -1e30f, -1e30f};
    float l_i[4] = {0.f, 0.f, 0.f, 0.f};
    float o[4][4] = {};

    const float* Ktb = g_Kt + (size_t)b * H_DIM * S_LEN;
    const float* Vb  = g_V  + (size_t)b * S_LEN * H_DIM;

    for (int j = 0; j <= qi; j++) {
        __syncthreads();   // previous PV done reading Vs/Ps; Q load done (iter 0)
        #pragma unroll
        for (int u = 0; u < 4; u++) {
            int t = tid + u * 256;
            int r = t >> 4, c = (t & 15) << 2;
            *(float4*)&Kst[r][c] = *(const float4*)&Ktb[(size_t)r * S_LEN + j * 64 + c];
            *(float4*)&Vs[r][c]  = *(const float4*)&Vb[(size_t)(j * 64 + r) * H_DIM + c];
        }
        __syncthreads();

        // S = Q @ K^T (pre-scaled)
        float s[4][4] = {};
        #pragma unroll 8
        for (int kk = 0; kk < 64; kk++) {
            float4 kv = *(float4*)&Kst[kk][tx << 2];
            #pragma unroll
            for (int ii = 0; ii < 4; ii++) {
                float q = Qs[(ty << 2) + ii][kk];
                s[ii][0] += q * kv.x; s[ii][1] += q * kv.y;
                s[ii][2] += q * kv.z; s[ii][3] += q * kv.w;
            }
        }

        // Causal mask on the diagonal tile
        if (j == qi) {
            #pragma unroll
            for (int ii = 0; ii < 4; ii++)
                #pragma unroll
                for (int jj = 0; jj < 4; jj++)
                    if (((tx << 2) + jj) > ((ty << 2) + ii)) s[ii][jj] = -1e30f;
        }

        // Online softmax (row reduction across the 16 tx lanes; xor<16 stays in-warp)
        #pragma unroll
        for (int ii = 0; ii < 4; ii++) {
            float mx = fmaxf(fmaxf(s[ii][0], s[ii][1]), fmaxf(s[ii][2], s[ii][3]));
            #pragma unroll
            for (int off = 1; off < 16; off <<= 1)
                mx = fmaxf(mx, __shfl_xor_sync(0xffffffffu, mx, off));
            float m_new = fmaxf(m_i[ii], mx);
            float corr  = __expf(m_i[ii] - m_new);
            float rs = 0.f;
            #pragma unroll
            for (int jj = 0; jj < 4; jj++) {
                float p = __expf(s[ii][jj] - m_new);
                rs += p;
                Ps[(ty << 2) + ii][(tx << 2) + jj] = p;
            }
            #pragma unroll
            for (int off = 1; off < 16; off <<= 1)
                rs += __shfl_xor_sync(0xffffffffu, rs, off);
            l_i[ii] = l_i[ii] * corr + rs;
            m_i[ii] = m_new;
            o[ii][0] *= corr; o[ii][1] *= corr; o[ii][2] *= corr; o[ii][3] *= corr;
        }
        __syncthreads();

        // O += P @ V
        #pragma unroll 8
        for (int kk = 0; kk < 64; kk++) {
            float4 vv = *(float4*)&Vs[kk][tx << 2];
            #pragma unroll
            for (int ii = 0; ii < 4; ii++) {
                float p = Ps[(ty << 2) + ii][kk];
                o[ii][0] += p * vv.x; o[ii][1] += p * vv.y;
                o[ii][2] += p * vv.z; o[ii][3] += p * vv.w;
            }
        }
    }

    // Normalize and store
    float* Op = g_O + ((size_t)(b * S_LEN + qi * 64)) * H_DIM;
    #pragma unroll
    for (int ii = 0; ii < 4; ii++) {
        float inv = 1.0f / l_i[ii];
        float4 ov = make_float4(o[ii][0] * inv, o[ii][1] * inv,
                                o[ii][2] * inv, o[ii][3] * inv);
        *(float4*)&Op[((ty << 2) + ii) * H_DIM + (tx << 2)] = ov;
    }
}

// ---------------------------------------------------------------------------
extern "C" void kernel_launch(void* const* d_in, const int* in_sizes, int n_in,
                              void* d_out, int out_size)
{
    const float* x  = (const float*)d_in[0];
    const float* Wq = (const float*)d_in[1];
    const float* bq = (const float*)d_in[2];
    const float* Wk = (const float*)d_in[3];
    const float* bk = (const float*)d_in[4];
    const float* Wv = (const float*)d_in[5];
    const float* bv = (const float*)d_in[6];
    const float* Wo = (const float*)d_in[7];
    const float* bo = (const float*)d_in[8];
    float* out = (float*)d_out;

    float *pQ, *pKt, *pV, *pO;
    cudaGetSymbolAddress((void**)&pQ,  g_Q);
    cudaGetSymbolAddress((void**)&pKt, g_Kt);
    cudaGetSymbolAddress((void**)&pV,  g_V);
    cudaGetSymbolAddress((void**)&pO,  g_O);

    dim3 blk(256);

    // Q/K/V projections: M=16384, K=512, N=64 (K projection scatters transposed)
    gemm_bias_kernel<<<dim3(1, NT / 64), blk>>>(x, Wq, bq, pQ,  NT, H_DIM, D_DIM, 0);
    gemm_bias_kernel<<<dim3(1, NT / 64), blk>>>(x, Wk, bk, pKt, NT, H_DIM, D_DIM, 1);
    gemm_bias_kernel<<<dim3(1, NT / 64), blk>>>(x, Wv, bv, pV,  NT, H_DIM, D_DIM, 0);

    // Fused causal attention
    cudaFuncSetAttribute(attn_kernel, cudaFuncAttributeMaxDynamicSharedMemorySize, 65536);
    attn_kernel<<<dim3(S_LEN / 64, B_SZ), blk, 65536>>>();

    // Output projection: M=16384, K=64, N=512
    gemm_bias_kernel<<<dim3(D_DIM / 64, NT / 64), blk>>>(pO, Wo, bo, out, NT, D_DIM, H_DIM, 0);
}

// round 13
// speedup vs baseline: 1.0010x; 1.0005x over previous
#include <cuda_runtime.h>

#define B_SZ   4
#define S_LEN  4096
#define D_DIM  512
#define H_DIM  64
#define NT     (B_SZ * S_LEN)   // 16384 total tokens

// Scratch (device globals — no allocations allowed in kernel_launch)
__device__ float g_Q [B_SZ * S_LEN * H_DIM];   // [b][s][h]
__device__ float g_Kt[B_SZ * H_DIM * S_LEN];   // [b][h][s]  (pre-transposed K)
__device__ float g_V [B_SZ * S_LEN * H_DIM];   // [b][s][h]
__device__ float g_O [B_SZ * S_LEN * H_DIM];   // [b][s][h]

// ---------------------------------------------------------------------------
// C[M,N] = A[M,K] @ W[K,N] + bias
// out_mode 0: C[m*N + n]
// out_mode 1: scatter to [b][n][s] with b = m / S_LEN, s = m % S_LEN  (K transpose)
// Requires M%64==0, N%64==0, K%64==0. Block = 256 threads, 64x64 tile, 4x4/thread.
// ---------------------------------------------------------------------------
__global__ __launch_bounds__(256) void gemm_bias_kernel(
    const float* __restrict__ A,
    const float* __restrict__ W,
    const float* __restrict__ bias,
    float* __restrict__ C,
    int M, int N, int K, int out_mode)
{
    __shared__ float As[64][64];
    __shared__ float Ws[64][64];
    const int tid = threadIdx.x;
    const int tx = tid & 15, ty = tid >> 4;
    const int m0 = blockIdx.y * 64;
    const int n0 = blockIdx.x * 64;

    float acc[4][4] = {};

    for (int k0 = 0; k0 < K; k0 += 64) {
        #pragma unroll
        for (int u = 0; u < 4; u++) {
            int t = tid + u * 256;
            int r = t >> 4, c = (t & 15) << 2;
            *(float4*)&As[r][c] = *(const float4*)&A[(size_t)(m0 + r) * K + k0 + c];
            *(float4*)&Ws[r][c] = *(const float4*)&W[(size_t)(k0 + r) * N + n0 + c];
        }
        __syncthreads();

        #pragma unroll 8
        for (int kk = 0; kk < 64; kk++) {
            float4 wv = *(float4*)&Ws[kk][tx << 2];
            float a0 = As[(ty << 2) + 0][kk];
            float a1 = As[(ty << 2) + 1][kk];
            float a2 = As[(ty << 2) + 2][kk];
            float a3 = As[(ty << 2) + 3][kk];
            acc[0][0] += a0 * wv.x; acc[0][1] += a0 * wv.y; acc[0][2] += a0 * wv.z; acc[0][3] += a0 * wv.w;
            acc[1][0] += a1 * wv.x; acc[1][1] += a1 * wv.y; acc[1][2] += a1 * wv.z; acc[1][3] += a1 * wv.w;
            acc[2][0] += a2 * wv.x; acc[2][1] += a2 * wv.y; acc[2][2] += a2 * wv.z; acc[2][3] += a2 * wv.w;
            acc[3][0] += a3 * wv.x; acc[3][1] += a3 * wv.y; acc[3][2] += a3 * wv.z; acc[3][3] += a3 * wv.w;
        }
        __syncthreads();
    }

    #pragma unroll
    for (int ii = 0; ii < 4; ii++) {
        int m = m0 + (ty << 2) + ii;
        #pragma unroll
        for (int jj = 0; jj < 4; jj++) {
            int n = n0 + (tx << 2) + jj;
            float v = acc[ii][jj] + bias[n];
            if (out_mode == 0) {
                C[(size_t)m * N + n] = v;
            } else {
                int b = m >> 12;            // S_LEN = 4096 = 2^12
                int s = m & 4095;
                C[(((size_t)(b * H_DIM + n)) << 12) + s] = v;
            }
        }
    }
}

// ---------------------------------------------------------------------------
// Fused causal flash attention over g_Q / g_Kt / g_V -> g_O.
// Br = Bc = 64, 256 threads (tx=k/h dim, ty=q dim), 4x4 per thread.
// Scores pre-scaled by 1/64 (reference divides by sqrt(S) = 64).
// Dynamic smem: Qs | Kst | Vs | Ps, 4 * 64*64 floats = 64 KB.
// ---------------------------------------------------------------------------
__global__ __launch_bounds__(256, 3) void attn_kernel()
{
    extern __shared__ float sm[];
    float (*Qs)[64]  = (float(*)[64])(sm);
    float (*Kst)[64] = (float(*)[64])(sm + 4096);   // [h][k]
    float (*Vs)[64]  = (float(*)[64])(sm + 8192);   // [k][h]
    float (*Ps)[64]  = (float(*)[64])(sm + 12288);  // [q][k]

    const int b   = blockIdx.y;
    const int qi  = (gridDim.x - 1) - blockIdx.x;   // longest blocks launch first
    const int tid = threadIdx.x;
    const int tx  = tid & 15, ty = tid >> 4;

    // Load Q tile, pre-scaled by 1/64
    const float* Qp = g_Q + ((size_t)(b * S_LEN + qi * 64)) * H_DIM;
    #pragma unroll
    for (int u = 0; u < 4; u++) {
        int t = tid + u * 256;
        int r = t >> 4, c = (t & 15) << 2;
        float4 q = *(const float4*)&Qp[r * H_DIM + c];
        q.x *= 0.015625f; q.y *= 0.015625f; q.z *= 0.015625f; q.w *= 0.015625f;
        *(float4*)&Qs[r][c] = q;
    }

    float m_i[4] = {-1e30f, -1e30f, -1e30f, -1e30f};
    float l_i[4] = {0.f, 0.f, 0.f, 0.f};
    float o[4][4] = {};

    const float* Ktb = g_Kt + (size_t)b * H_DIM * S_LEN;
    const float* Vb  = g_V  + (size_t)b * S_LEN * H_DIM;

    for (int j = 0; j <= qi; j++) {
        __syncthreads();   // previous PV done reading Vs/Ps; Q load done (iter 0)
        #pragma unroll
        for (int u = 0; u < 4; u++) {
            int t = tid + u * 256;
            int r = t >> 4, c = (t & 15) << 2;
            *(float4*)&Kst[r][c] = *(const float4*)&Ktb[(size_t)r * S_LEN + j * 64 + c];
            *(float4*)&Vs[r][c]  = *(const float4*)&Vb[(size_t)(j * 64 + r) * H_DIM + c];
        }
        __syncthreads();

        // S = Q @ K^T (pre-scaled)
        float s[4][4] = {};
        #pragma unroll 8
        for (int kk = 0; kk < 64; kk++) {
            float4 kv = *(float4*)&Kst[kk][tx << 2];
            #pragma unroll
            for (int ii = 0; ii < 4; ii++) {
                float q = Qs[(ty << 2) + ii][kk];
                s[ii][0] += q * kv.x; s[ii][1] += q * kv.y;
                s[ii][2] += q * kv.z; s[ii][3] += q * kv.w;
            }
        }

        // Causal mask on the diagonal tile
        if (j == qi) {
            #pragma unroll
            for (int ii = 0; ii < 4; ii++)
                #pragma unroll
                for (int jj = 0; jj < 4; jj++)
                    if (((tx << 2) + jj) > ((ty << 2) + ii)) s[ii][jj] = -1e30f;
        }

        // Online softmax (row reduction across the 16 tx lanes; xor<16 stays in-warp)
        #pragma unroll
        for (int ii = 0; ii < 4; ii++) {
            float mx = fmaxf(fmaxf(s[ii][0], s[ii][1]), fmaxf(s[ii][2], s[ii][3]));
            #pragma unroll
            for (int off = 1; off < 16; off <<= 1)
                mx = fmaxf(mx, __shfl_xor_sync(0xffffffffu, mx, off));
            float m_new = fmaxf(m_i[ii], mx);
            float corr  = __expf(m_i[ii] - m_new);
            float rs = 0.f;
            #pragma unroll
            for (int jj = 0; jj < 4; jj++) {
                float p = __expf(s[ii][jj] - m_new);
                rs += p;
                Ps[(ty << 2) + ii][(tx << 2) + jj] = p;
            }
            #pragma unroll
            for (int off = 1; off < 16; off <<= 1)
                rs += __shfl_xor_sync(0xffffffffu, rs, off);
            l_i[ii] = l_i[ii] * corr + rs;
            m_i[ii] = m_new;
            o[ii][0] *= corr; o[ii][1] *= corr; o[ii][2] *= corr; o[ii][3] *= corr;
        }
        __syncthreads();

        // O += P @ V
        #pragma unroll 8
        for (int kk = 0; kk < 64; kk++) {
            float4 vv = *(float4*)&Vs[kk][tx << 2];
            #pragma unroll
            for (int ii = 0; ii < 4; ii++) {
                float p = Ps[(ty << 2) + ii][kk];
                o[ii][0] += p * vv.x; o[ii][1] += p * vv.y;
                o[ii][2] += p * vv.z; o[ii][3] += p * vv.w;
            }
        }
    }

    // Normalize and store
    float* Op = g_O + ((size_t)(b * S_LEN + qi * 64)) * H_DIM;
    #pragma unroll
    for (int ii = 0; ii < 4; ii++) {
        float inv = 1.0f / l_i[ii];
        float4 ov = make_float4(o[ii][0] * inv, o[ii][1] * inv,
                                o[ii][2] * inv, o[ii][3] * inv);
        *(float4*)&Op[((ty << 2) + ii) * H_DIM + (tx << 2)] = ov;
    }
}

// ---------------------------------------------------------------------------
extern "C" void kernel_launch(void* const* d_in, const int* in_sizes, int n_in,
                              void* d_out, int out_size)
{
    const float* x  = (const float*)d_in[0];
    const float* Wq = (const float*)d_in[1];
    const float* bq = (const float*)d_in[2];
    const float* Wk = (const float*)d_in[3];
    const float* bk = (const float*)d_in[4];
    const float* Wv = (const float*)d_in[5];
    const float* bv = (const float*)d_in[6];
    const float* Wo = (const float*)d_in[7];
    const float* bo = (const float*)d_in[8];
    float* out = (float*)d_out;

    float *pQ, *pKt, *pV, *pO;
    cudaGetSymbolAddress((void**)&pQ,  g_Q);
    cudaGetSymbolAddress((void**)&pKt, g_Kt);
    cudaGetSymbolAddress((void**)&pV,  g_V);
    cudaGetSymbolAddress((void**)&pO,  g_O);

    dim3 blk(256);

    // Q/K/V projections: M=16384, K=512, N=64 (K projection scatters transposed)
    gemm_bias_kernel<<<dim3(1, NT / 64), blk>>>(x, Wq, bq, pQ,  NT, H_DIM, D_DIM, 0);
    gemm_bias_kernel<<<dim3(1, NT / 64), blk>>>(x, Wk, bk, pKt, NT, H_DIM, D_DIM, 1);
    gemm_bias_kernel<<<dim3(1, NT / 64), blk>>>(x, Wv, bv, pV,  NT, H_DIM, D_DIM, 0);

    // Fused causal attention
    cudaFuncSetAttribute(attn_kernel, cudaFuncAttributeMaxDynamicSharedMemorySize, 65536);
    attn_kernel<<<dim3(S_LEN / 64, B_SZ), blk, 65536>>>();

    // Output projection: M=16384, K=64, N=512
    gemm_bias_kernel<<<dim3(D_DIM / 64, NT / 64), blk>>>(pO, Wo, bo, out, NT, D_DIM, H_DIM, 0);
}